// round 10
// baseline (speedup 1.0000x reference)
#include <cuda_runtime.h>
#include <cuda_fp16.h>
#include <cstdint>

// Problem constants
constexpr int Bb  = 2;
constexpr int Cc  = 256;
constexpr int Hh  = 56;
constexpr int Ww  = 96;
constexpr int HWv = Hh * Ww;          // 5376
constexpr int Nn  = Bb * HWv;         // 10752

// Pyramid dims
constexpr int H1 = 28, W1 = 48;
constexpr int H2 = 14, W2 = 24;
constexpr int H3 = 7,  W3 = 12;

// fp16 channels-last maps: query map + fmap2 pyramid; compact corr scratch
__device__ __half g_f1h[(size_t)Bb * HWv * Cc];
__device__ __half g_f20[(size_t)Bb * HWv * Cc];
__device__ __half g_f21[(size_t)Bb * H1 * W1 * Cc];
__device__ __half g_f22[(size_t)Bb * H2 * W2 * Cc];
__device__ __half g_f23[(size_t)Bb * H3 * W3 * Cc];
__device__ float  g_corr[(size_t)Nn * 324];

// ---------------------------------------------------------------------------
// Transpose [B, C, HW] -> [B, HW, C] with fp32 -> fp16 convert
// ---------------------------------------------------------------------------
__global__ void transpose_h_k(const float* __restrict__ in, int which) {
    __shared__ float tile[32][33];
    __half* out = which ? g_f20 : g_f1h;
    int b   = blockIdx.z;
    int hw0 = blockIdx.x * 32;
    int c0  = blockIdx.y * 32;
    const float* ib = in  + (size_t)b * Cc * HWv;
    __half*      ob = out + (size_t)b * HWv * Cc;
    int tx = threadIdx.x, ty = threadIdx.y;   // 32 x 8
#pragma unroll
    for (int r = 0; r < 32; r += 8)
        tile[ty + r][tx] = ib[(size_t)(c0 + ty + r) * HWv + hw0 + tx];
    __syncthreads();
#pragma unroll
    for (int r = 0; r < 32; r += 8)
        ob[(size_t)(hw0 + ty + r) * Cc + c0 + tx] = __float2half_rn(tile[tx][ty + r]);
}

// ---------------------------------------------------------------------------
// 2x2 avg pool on channels-last fp16 layout. 128 threads = 128 half2 lanes.
// ---------------------------------------------------------------------------
__global__ void pool_k(int level) {
    const __half* in; __half* out; int Wi, Wo, Ho;
    if (level == 1)      { in = g_f20; out = g_f21; Wi = 96; Wo = 48; Ho = 28; }
    else if (level == 2) { in = g_f21; out = g_f22; Wi = 48; Wo = 24; Ho = 14; }
    else                 { in = g_f22; out = g_f23; Wi = 24; Wo = 12; Ho = 7;  }
    int HiWi = (2 * Ho) * Wi;
    int HoWo = Ho * Wo;
    int b = blockIdx.y, p = blockIdx.x, c = threadIdx.x;   // c in [0,128) half2 units
    int y = p / Wo, x = p - y * Wo;
    const __half2* ib = (const __half2*)(in + (size_t)b * HiWi * Cc);
    size_t i00 = ((size_t)(2 * y) * Wi + 2 * x) * (Cc / 2) + c;
    size_t rs  = (size_t)Wi * (Cc / 2);
    float2 v0 = __half22float2(ib[i00]);
    float2 v1 = __half22float2(ib[i00 + Cc / 2]);
    float2 v2 = __half22float2(ib[i00 + rs]);
    float2 v3 = __half22float2(ib[i00 + rs + Cc / 2]);
    float2 s;
    s.x = 0.25f * (v0.x + v1.x + v2.x + v3.x);
    s.y = 0.25f * (v0.y + v1.y + v2.y + v3.y);
    ((__half2*)(out + ((size_t)b * HoWo + p) * Cc))[c] = __floats2half2_rn(s.x, s.y);
}

// ---------------------------------------------------------------------------
// Correlation lookup via tensor cores, tiled + cp.async double-buffered.
// One block = 2x2 pixel tile, 256 threads = 8 warps.
// 16 tasks per block (4 levels x 4 pixels, level-major for window overlap /
// L1 reuse). Per task: stage 112 gathered fp16 columns into a SMEM buffer
// via cp.async.ca (14 x 16B per lane, deep MLP, no register round trip),
// double-buffered against the MMA of the previous task. MMA: 7 m16n8k16
// tiles (warps 0-6), query replicated across n, col 0 extracted.
// ---------------------------------------------------------------------------
constexpr int ASTR = 264;            // halves per staged row (528B, bank-shifted)
constexpr int BUFH = 112 * ASTR;     // halves per buffer
constexpr int LK_DSMEM = 2 * BUFH * 2;  // bytes of dynamic SMEM (118272)

__global__ __launch_bounds__(256) void lookup_k(const float* __restrict__ coords) {
    extern __shared__ __align__(16) __half dbuf[];   // [2][BUFH]
    __shared__ __half   sQ[4 * 256];      // 4 queries fp16
    __shared__ float    sVal[16 * 112];   // validity * 1/sqrt(C) per task/pos
    __shared__ unsigned sOff[16 * 112];   // clamped column offsets (half units)
    __shared__ float    sD[104];          // window dots of current task
    __shared__ float    sWxy[32];         // (wx, wy) per task
    __shared__ int      sRem[4];
    __shared__ const __half* sBase[16];

    int b   = blockIdx.z;
    int x0b = blockIdx.x * 2, y0b = blockIdx.y * 2;
    int t = threadIdx.x, w = t >> 5, lane = t & 31;

    const __half* lp[4] = { g_f20, g_f21, g_f22, g_f23 };

    // load 4 queries (512B each) into SMEM
    for (int i = t; i < 512; i += 256) {
        int p = i >> 7, u = i & 127;
        int rem = (y0b + (p >> 1)) * Ww + x0b + (p & 1);
        ((unsigned*)sQ)[i] =
            ((const unsigned*)(g_f1h + (size_t)(b * HWv + rem) * Cc))[u];
    }
    if (t < 4) sRem[t] = (y0b + (t >> 1)) * Ww + x0b + (t & 1);
    if (t < 16) {
        int l = t >> 2, p = t & 3;
        int rem = (y0b + (p >> 1)) * Ww + x0b + (p & 1);
        float inv = 1.f / (float)(1 << l);
        float px = coords[(size_t)b * 2 * HWv + rem] * inv;
        float py = coords[(size_t)b * 2 * HWv + HWv + rem] * inv;
        sWxy[2 * t]     = px - floorf(px);
        sWxy[2 * t + 1] = py - floorf(py);
        sBase[t] = lp[l] + (size_t)b * (Hh >> l) * (Ww >> l) * Cc;
    }
    // precompute offsets + validity for all 16 tasks x 112 (padded) positions
    for (int e = t; e < 16 * 112; e += 256) {
        int task = e / 112, pos = e - task * 112;
        int l = task >> 2, p = task & 3;
        int rem = (y0b + (p >> 1)) * Ww + x0b + (p & 1);
        float inv = 1.f / (float)(1 << l);
        int x0 = (int)floorf(coords[(size_t)b * 2 * HWv + rem] * inv);
        int y0 = (int)floorf(coords[(size_t)b * 2 * HWv + HWv + rem] * inv);
        int Hl = Hh >> l, Wl = Ww >> l;
        int pc = min(pos, 99);
        int xi = pc / 10, yj = pc - xi * 10;
        int gx = x0 - 4 + xi, gy = y0 - 4 + yj;
        bool valid = (gx >= 0) & (gx < Wl) & (gy >= 0) & (gy < Hl) & (pos < 100);
        int cgx = min(max(gx, 0), Wl - 1);
        int cgy = min(max(gy, 0), Hl - 1);
        sOff[e] = (unsigned)((cgy * Wl + cgx) * Cc);
        sVal[e] = valid ? 0.0625f : 0.f;   // fold 1/sqrt(256)
    }
    __syncthreads();

    unsigned dsb = (unsigned)__cvta_generic_to_shared(dbuf);

    // stage task 0 into buffer 0
    {
        const __half* base = sBase[0];
#pragma unroll
        for (int i = 0; i < 14; i++) {
            int c = i * 8 + w;
            unsigned sa = dsb + (unsigned)((c * ASTR + lane * 8) * 2);
            const __half* src = base + sOff[c] + lane * 8;
            asm volatile("cp.async.ca.shared.global [%0], [%1], 16;"
                         :: "r"(sa), "l"(src));
        }
        asm volatile("cp.async.commit_group;");
    }

#pragma unroll 1
    for (int task = 0; task < 16; task++) {
        unsigned curb = dsb + (unsigned)((task & 1) * (BUFH * 2));
        if (task + 1 < 16) {
            unsigned nxtb = dsb + (unsigned)(((task + 1) & 1) * (BUFH * 2));
            const __half* base = sBase[task + 1];
            const unsigned* offs = sOff + (task + 1) * 112;
#pragma unroll
            for (int i = 0; i < 14; i++) {
                int c = i * 8 + w;
                unsigned sa = nxtb + (unsigned)((c * ASTR + lane * 8) * 2);
                const __half* src = base + offs[c] + lane * 8;
                asm volatile("cp.async.ca.shared.global [%0], [%1], 16;"
                             :: "r"(sa), "l"(src));
            }
            asm volatile("cp.async.commit_group;");
            asm volatile("cp.async.wait_group 1;");
        } else {
            asm volatile("cp.async.wait_group 0;");
        }
        __syncthreads();

        int l = task >> 2, p = task & 3;
        float acc0 = 0.f, acc1 = 0.f, acc2 = 0.f, acc3 = 0.f;
        if (w < 7) {
            unsigned arow = curb + (unsigned)(((w * 16 + (lane & 15)) * ASTR
                                + ((lane >> 4) << 3)) * 2);
            const __half* q = sQ + p * 256;
#pragma unroll
            for (int ks = 0; ks < 16; ks++) {
                unsigned a0, a1, a2, a3;
                asm volatile(
                    "ldmatrix.sync.aligned.m8n8.x4.shared.b16 {%0,%1,%2,%3}, [%4];"
                    : "=r"(a0), "=r"(a1), "=r"(a2), "=r"(a3)
                    : "r"(arow + (unsigned)(ks * 32)));
                unsigned bq0 = *(const unsigned*)&q[ks * 16 + 2 * (lane & 3)];
                unsigned bq1 = *(const unsigned*)&q[ks * 16 + 2 * (lane & 3) + 8];
                asm volatile(
                    "mma.sync.aligned.m16n8k16.row.col.f32.f16.f16.f32 "
                    "{%0,%1,%2,%3}, {%4,%5,%6,%7}, {%8,%9}, {%0,%1,%2,%3};"
                    : "+f"(acc0), "+f"(acc1), "+f"(acc2), "+f"(acc3)
                    : "r"(a0), "r"(a1), "r"(a2), "r"(a3), "r"(bq0), "r"(bq1));
            }
        }
        // extraction: col 0 lives in lanes with lane%4==0 (acc0 row r, acc2 row r+8)
        const float* val = sVal + task * 112;
        if (w < 7 && (lane & 3) == 0) {
            int r0 = w * 16 + (lane >> 2);
            if (r0 < 100) sD[r0] = acc0 * val[r0];
            int r1 = r0 + 8;
            if (r1 < 100) sD[r1] = acc2 * val[r1];
        }
        __syncthreads();

        if (t < 81) {
            float wxp = sWxy[2 * task], wyp = sWxy[2 * task + 1];
            int ix = t / 9, iy = t - ix * 9;
            float d00 = sD[ix * 10 + iy];
            float d10 = sD[ix * 10 + 10 + iy];
            float d01 = sD[ix * 10 + iy + 1];
            float d11 = sD[ix * 10 + 11 + iy];
            float v = (1.f - wyp) * ((1.f - wxp) * d00 + wxp * d10)
                    +        wyp  * ((1.f - wxp) * d01 + wxp * d11);
            g_corr[((size_t)b * HWv + sRem[p]) * 324 + l * 81 + t] = v;
        }
        __syncthreads();   // protect sD and the buffer being re-staged next iter
    }
}

// ---------------------------------------------------------------------------
// Transpose compact corr [B*HW][324] -> out [B][324][HW] (coalesced both sides)
// ---------------------------------------------------------------------------
__global__ void corr_t_k(float* __restrict__ out) {
    __shared__ float tile[32][33];
    int b  = blockIdx.z;
    int r0 = blockIdx.x * 32;   // rem tile
    int c0 = blockIdx.y * 32;   // channel tile (0..323)
    int tx = threadIdx.x, ty = threadIdx.y;   // 32 x 8
#pragma unroll
    for (int r = 0; r < 32; r += 8) {
        int c = c0 + tx;
        float v = 0.f;
        if (c < 324)
            v = g_corr[((size_t)b * HWv + r0 + ty + r) * 324 + c];
        tile[ty + r][tx] = v;
    }
    __syncthreads();
#pragma unroll
    for (int r = 0; r < 32; r += 8) {
        int c = c0 + ty + r;
        if (c < 324)
            out[((size_t)b * 324 + c) * HWv + r0 + tx] = tile[tx][ty + r];
    }
}

// ---------------------------------------------------------------------------
// Convex upsample, coalesced. One block = 32 consecutive coarse pixels in a
// row. 256 threads: warp = subpixel row p8, lane = pixel.
// ---------------------------------------------------------------------------
__global__ __launch_bounds__(256) void upsample_k(const float* __restrict__ flow,
                                                  const float* __restrict__ mask,
                                                  float* __restrict__ out) {
    int rem0 = blockIdx.x * 32;
    int b  = rem0 / HWv;
    int r  = rem0 - b * HWv;
    int y  = r / Ww;
    int x0 = r - y * Ww;

    __shared__ float pfc[2][3][34];   // 3x3 neighborhoods of 8*flow for 32 pixels
    int t = threadIdx.x;
    if (t < 204) {
        int ch = t / 102, q = t - ch * 102;
        int dy = q / 34,  dx = q - dy * 34;
        int gy = y - 1 + dy, gx = x0 - 1 + dx;
        float v = 0.f;
        if (gy >= 0 && gy < Hh && gx >= 0 && gx < Ww)
            v = 8.f * flow[((size_t)b * 2 + ch) * HWv + gy * Ww + gx];
        pfc[ch][dy][dx] = v;
    }
    __syncthreads();

    int w = t >> 5;        // p8 (subpixel row)
    int lane = t & 31;     // pixel within the 32-pixel strip
    int rem = r + lane;
    const float* mb = mask + (size_t)b * 576 * HWv + rem;

    float o0[8], o1[8];
#pragma unroll
    for (int q8 = 0; q8 < 8; q8++) {
        float mv[9];
        float mmax = -1e30f;
#pragma unroll
        for (int k = 0; k < 9; k++) {
            mv[k] = mb[(size_t)(k * 64 + w * 8 + q8) * HWv];
            mmax = fmaxf(mmax, mv[k]);
        }
        float se = 0.f;
#pragma unroll
        for (int k = 0; k < 9; k++) { mv[k] = __expf(mv[k] - mmax); se += mv[k]; }
        float rr = 1.f / se;
        float s0 = 0.f, s1 = 0.f;
#pragma unroll
        for (int k = 0; k < 9; k++) {
            int i = k / 3, j = k - i * 3;
            s0 += mv[k] * pfc[0][i][lane + j];
            s1 += mv[k] * pfc[1][i][lane + j];
        }
        o0[q8] = s0 * rr;
        o1[q8] = s1 * rr;
    }

    size_t OFFU  = (size_t)Bb * 324 * HWv;
    size_t plane = (size_t)(Hh * 8) * (Ww * 8);
    int oy = y * 8 + w;
    float* p0 = out + OFFU + (size_t)b * 2 * plane
              + (size_t)oy * (Ww * 8) + (size_t)(x0 + lane) * 8;
    ((float4*)p0)[0] = make_float4(o0[0], o0[1], o0[2], o0[3]);
    ((float4*)p0)[1] = make_float4(o0[4], o0[5], o0[6], o0[7]);
    float* p1 = p0 + plane;
    ((float4*)p1)[0] = make_float4(o1[0], o1[1], o1[2], o1[3]);
    ((float4*)p1)[1] = make_float4(o1[4], o1[5], o1[6], o1[7]);
}

// ---------------------------------------------------------------------------
extern "C" void kernel_launch(void* const* d_in, const int* in_sizes, int n_in,
                              void* d_out, int out_size) {
    const float* fmap1  = (const float*)d_in[0];
    const float* fmap2  = (const float*)d_in[1];
    const float* coords = (const float*)d_in[2];
    const float* flow   = (const float*)d_in[3];
    const float* mask   = (const float*)d_in[4];
    float* out = (float*)d_out;

    cudaFuncSetAttribute(lookup_k,
                         cudaFuncAttributeMaxDynamicSharedMemorySize, LK_DSMEM);

    dim3 tb(32, 8);
    dim3 tg(HWv / 32, Cc / 32, Bb);
    transpose_h_k<<<tg, tb>>>(fmap1, 0);
    transpose_h_k<<<tg, tb>>>(fmap2, 1);
    pool_k<<<dim3(H1 * W1, Bb), 128>>>(1);
    pool_k<<<dim3(H2 * W2, Bb), 128>>>(2);
    pool_k<<<dim3(H3 * W3, Bb), 128>>>(3);
    lookup_k<<<dim3(Ww / 2, Hh / 2, Bb), 256, LK_DSMEM>>>(coords);
    corr_t_k<<<dim3(HWv / 32, 11, Bb), tb>>>(out);
    upsample_k<<<Nn / 32, 256>>>(flow, mask, out);
}

// round 11
// speedup vs baseline: 1.2198x; 1.2198x over previous
#include <cuda_runtime.h>
#include <cuda_fp16.h>

// Problem constants
constexpr int Bb  = 2;
constexpr int Cc  = 256;
constexpr int Hh  = 56;
constexpr int Ww  = 96;
constexpr int HWv = Hh * Ww;          // 5376
constexpr int Nn  = Bb * HWv;         // 10752

// Pyramid dims
constexpr int H1 = 28, W1 = 48;
constexpr int H2 = 14, W2 = 24;
constexpr int H3 = 7,  W3 = 12;

// Scratch: fp32 transposed query map; fp16 channels-last fmap2 pyramid;
// compact per-pixel corr output staged for a coalescing transpose
__device__ float  g_f1t[(size_t)Bb * HWv * Cc];
__device__ __half g_f20[(size_t)Bb * HWv * Cc];
__device__ __half g_f21[(size_t)Bb * H1 * W1 * Cc];
__device__ __half g_f22[(size_t)Bb * H2 * W2 * Cc];
__device__ __half g_f23[(size_t)Bb * H3 * W3 * Cc];
__device__ float  g_corr[(size_t)Nn * 324];

// ---------------------------------------------------------------------------
// Transpose [B, C, HW] -> [B, HW, C] fp32 (query map)
// ---------------------------------------------------------------------------
__global__ void transpose_f_k(const float* __restrict__ in) {
    __shared__ float tile[32][33];
    int b   = blockIdx.z;
    int hw0 = blockIdx.x * 32;
    int c0  = blockIdx.y * 32;
    const float* ib = in     + (size_t)b * Cc * HWv;
    float*       ob = g_f1t  + (size_t)b * HWv * Cc;
    int tx = threadIdx.x, ty = threadIdx.y;   // 32 x 8
#pragma unroll
    for (int r = 0; r < 32; r += 8)
        tile[ty + r][tx] = ib[(size_t)(c0 + ty + r) * HWv + hw0 + tx];
    __syncthreads();
#pragma unroll
    for (int r = 0; r < 32; r += 8)
        ob[(size_t)(hw0 + ty + r) * Cc + c0 + tx] = tile[tx][ty + r];
}

// ---------------------------------------------------------------------------
// Transpose [B, C, HW] -> [B, HW, C] with fp32 -> fp16 convert (fmap2 base)
// ---------------------------------------------------------------------------
__global__ void transpose_h_k(const float* __restrict__ in) {
    __shared__ float tile[32][33];
    int b   = blockIdx.z;
    int hw0 = blockIdx.x * 32;
    int c0  = blockIdx.y * 32;
    const float* ib = in    + (size_t)b * Cc * HWv;
    __half*      ob = g_f20 + (size_t)b * HWv * Cc;
    int tx = threadIdx.x, ty = threadIdx.y;   // 32 x 8
#pragma unroll
    for (int r = 0; r < 32; r += 8)
        tile[ty + r][tx] = ib[(size_t)(c0 + ty + r) * HWv + hw0 + tx];
    __syncthreads();
#pragma unroll
    for (int r = 0; r < 32; r += 8)
        ob[(size_t)(hw0 + ty + r) * Cc + c0 + tx] = __float2half_rn(tile[tx][ty + r]);
}

// ---------------------------------------------------------------------------
// 2x2 avg pool on channels-last fp16 layout. 128 threads = 128 half2 lanes.
// ---------------------------------------------------------------------------
__global__ void pool_k(int level) {
    const __half* in; __half* out; int Wi, Wo, Ho;
    if (level == 1)      { in = g_f20; out = g_f21; Wi = 96; Wo = 48; Ho = 28; }
    else if (level == 2) { in = g_f21; out = g_f22; Wi = 48; Wo = 24; Ho = 14; }
    else                 { in = g_f22; out = g_f23; Wi = 24; Wo = 12; Ho = 7;  }
    int HiWi = (2 * Ho) * Wi;
    int HoWo = Ho * Wo;
    int b = blockIdx.y, p = blockIdx.x, c = threadIdx.x;   // c in [0,128) half2 units
    int y = p / Wo, x = p - y * Wo;
    const __half2* ib = (const __half2*)(in + (size_t)b * HiWi * Cc);
    size_t i00 = ((size_t)(2 * y) * Wi + 2 * x) * (Cc / 2) + c;
    size_t rs  = (size_t)Wi * (Cc / 2);
    float2 v0 = __half22float2(ib[i00]);
    float2 v1 = __half22float2(ib[i00 + Cc / 2]);
    float2 v2 = __half22float2(ib[i00 + rs]);
    float2 v3 = __half22float2(ib[i00 + rs + Cc / 2]);
    float2 s;
    s.x = 0.25f * (v0.x + v1.x + v2.x + v3.x);
    s.y = 0.25f * (v0.y + v1.y + v2.y + v3.y);
    ((__half2*)(out + ((size_t)b * HoWo + p) * Cc))[c] = __floats2half2_rn(s.x, s.y);
}

// ---------------------------------------------------------------------------
// Correlation lookup — warp-autonomous. One block = 4x2 tile of 8 pixels,
// 8 warps; warp w owns pixel w entirely. Each warp = four 8-lane dot groups
// -> 4 dots/iteration, 25 iterations cover the 100-position window per
// level (exactly, no padding). Bilinear epilogue done by the owning warp.
// NO block-wide barriers: only __syncwarp(). Warps drift independently
// across levels, maximizing latency/issue overlap; the 8 overlapping
// windows on one SM give L1 dedup of column reads.
// ---------------------------------------------------------------------------
__global__ __launch_bounds__(256) void lookup_k(const float* __restrict__ coords) {
    __shared__ float sD[8][104];   // per-warp window dots (10x10)

    int b   = blockIdx.z;
    int t    = threadIdx.x;
    int w    = t >> 5;            // warp 0..7 = pixel within 4x2 tile
    int lane = t & 31;
    int sub  = lane >> 3;         // dot slot within warp 0..3
    int li   = lane & 7;          // lane within dot group 0..7

    int pxx = blockIdx.x * 4 + (w & 3);
    int pyy = blockIdx.y * 2 + (w >> 2);
    int rem = pyy * Ww + pxx;
    int n   = b * HWv + rem;

    // Query vector chunk: lane li owns channels [li*32, li*32+32), fp32
    const float4* f1v = (const float4*)(g_f1t + (size_t)n * Cc) + li * 8;
    float a[32];
#pragma unroll
    for (int k = 0; k < 8; k++) {
        float4 q = f1v[k];
        a[4 * k]     = q.x;
        a[4 * k + 1] = q.y;
        a[4 * k + 2] = q.z;
        a[4 * k + 3] = q.w;
    }

    float cx = coords[(size_t)b * 2 * HWv + rem];
    float cy = coords[(size_t)b * 2 * HWv + HWv + rem];

    const __half* lp[4] = { g_f20, g_f21, g_f22, g_f23 };
    const int Hs[4] = { Hh, H1, H2, H3 };
    const int Ws[4] = { Ww, W1, W2, W3 };

#pragma unroll 1
    for (int l = 0; l < 4; l++) {
        float inv = 1.0f / (float)(1 << l);
        float px = cx * inv, py = cy * inv;
        float fx = floorf(px), fy = floorf(py);
        int x0 = (int)fx, y0 = (int)fy;
        float wx = px - fx, wy = py - fy;
        int Hl = Hs[l], Wl = Ws[l];
        const __half* base = lp[l] + (size_t)b * Hl * Wl * Cc;

        // 4 dot-slots per iteration; 25 iterations cover all 100 positions
#pragma unroll 1
        for (int it = 0; it < 25; it++) {
            int d  = it * 4 + sub;          // 0..99, always valid index
            int xi = d / 10, yj = d - xi * 10;
            int gx = x0 - 4 + xi;
            int gy = y0 - 4 + yj;
            bool valid = (gx >= 0) & (gx < Wl) & (gy >= 0) & (gy < Hl);
            int cgx = min(max(gx, 0), Wl - 1);
            int cgy = min(max(gy, 0), Hl - 1);
            // fp16 column: 512B; lane li reads 4 x 16B (= 32 channels)
            const uint4* col =
                (const uint4*)(base + ((size_t)cgy * Wl + cgx) * Cc) + li * 4;
            float s0 = 0.f, s1 = 0.f;
#pragma unroll
            for (int k = 0; k < 4; k++) {
                uint4 r = col[k];
                const __half2* h = reinterpret_cast<const __half2*>(&r);
#pragma unroll
                for (int j = 0; j < 4; j++) {
                    float2 f = __half22float2(h[j]);
                    s0 = fmaf(a[k * 8 + 2 * j],     f.x, s0);
                    s1 = fmaf(a[k * 8 + 2 * j + 1], f.y, s1);
                }
            }
            float s = s0 + s1;
            s = valid ? s : 0.f;
            // reduce within 8-lane group (all lanes converged)
            s += __shfl_xor_sync(0xffffffffu, s, 1);
            s += __shfl_xor_sync(0xffffffffu, s, 2);
            s += __shfl_xor_sync(0xffffffffu, s, 4);
            if (li == 0) sD[w][d] = s * 0.0625f;   // 1/sqrt(256)
        }
        __syncwarp();

        // bilinear combine: owning warp emits its 81 outputs (coalesced:
        // consecutive lanes hit consecutive addresses in g_corr)
        for (int u = lane; u < 81; u += 32) {
            int ix = u / 9, iy = u - ix * 9;
            float d00 = sD[w][ix * 10 + iy];
            float d10 = sD[w][ix * 10 + 10 + iy];
            float d01 = sD[w][ix * 10 + iy + 1];
            float d11 = sD[w][ix * 10 + 11 + iy];
            float v = (1.f - wy) * ((1.f - wx) * d00 + wx * d10)
                    +        wy  * ((1.f - wx) * d01 + wx * d11);
            g_corr[(size_t)n * 324 + l * 81 + u] = v;
        }
        __syncwarp();   // all lanes done reading sD[w] before next level writes
    }
}

// ---------------------------------------------------------------------------
// Transpose compact corr [B*HW][324] -> out [B][324][HW] (coalesced both sides)
// ---------------------------------------------------------------------------
__global__ void corr_t_k(float* __restrict__ out) {
    __shared__ float tile[32][33];
    int b  = blockIdx.z;
    int r0 = blockIdx.x * 32;   // rem tile
    int c0 = blockIdx.y * 32;   // channel tile (0..323)
    int tx = threadIdx.x, ty = threadIdx.y;   // 32 x 8
#pragma unroll
    for (int r = 0; r < 32; r += 8) {
        int c = c0 + tx;
        float v = 0.f;
        if (c < 324)
            v = g_corr[((size_t)b * HWv + r0 + ty + r) * 324 + c];
        tile[ty + r][tx] = v;
    }
    __syncthreads();
#pragma unroll
    for (int r = 0; r < 32; r += 8) {
        int c = c0 + ty + r;
        if (c < 324)
            out[((size_t)b * 324 + c) * HWv + r0 + tx] = tile[tx][ty + r];
    }
}

// ---------------------------------------------------------------------------
// Convex upsample, coalesced. One block = 32 consecutive coarse pixels in a
// row. 256 threads: warp = subpixel row p8, lane = pixel.
// ---------------------------------------------------------------------------
__global__ __launch_bounds__(256) void upsample_k(const float* __restrict__ flow,
                                                  const float* __restrict__ mask,
                                                  float* __restrict__ out) {
    int rem0 = blockIdx.x * 32;
    int b  = rem0 / HWv;
    int r  = rem0 - b * HWv;
    int y  = r / Ww;
    int x0 = r - y * Ww;

    __shared__ float pfc[2][3][34];   // 3x3 neighborhoods of 8*flow for 32 pixels
    int t = threadIdx.x;
    if (t < 204) {
        int ch = t / 102, q = t - ch * 102;
        int dy = q / 34,  dx = q - dy * 34;
        int gy = y - 1 + dy, gx = x0 - 1 + dx;
        float v = 0.f;
        if (gy >= 0 && gy < Hh && gx >= 0 && gx < Ww)
            v = 8.f * flow[((size_t)b * 2 + ch) * HWv + gy * Ww + gx];
        pfc[ch][dy][dx] = v;
    }
    __syncthreads();

    int w = t >> 5;        // p8 (subpixel row)
    int lane = t & 31;     // pixel within the 32-pixel strip
    int rem = r + lane;
    const float* mb = mask + (size_t)b * 576 * HWv + rem;

    float o0[8], o1[8];
#pragma unroll
    for (int q8 = 0; q8 < 8; q8++) {
        float mv[9];
        float mmax = -1e30f;
#pragma unroll
        for (int k = 0; k < 9; k++) {
            mv[k] = mb[(size_t)(k * 64 + w * 8 + q8) * HWv];
            mmax = fmaxf(mmax, mv[k]);
        }
        float se = 0.f;
#pragma unroll
        for (int k = 0; k < 9; k++) { mv[k] = __expf(mv[k] - mmax); se += mv[k]; }
        float rr = 1.f / se;
        float s0 = 0.f, s1 = 0.f;
#pragma unroll
        for (int k = 0; k < 9; k++) {
            int i = k / 3, j = k - i * 3;
            s0 += mv[k] * pfc[0][i][lane + j];
            s1 += mv[k] * pfc[1][i][lane + j];
        }
        o0[q8] = s0 * rr;
        o1[q8] = s1 * rr;
    }

    size_t OFFU  = (size_t)Bb * 324 * HWv;
    size_t plane = (size_t)(Hh * 8) * (Ww * 8);
    int oy = y * 8 + w;
    float* p0 = out + OFFU + (size_t)b * 2 * plane
              + (size_t)oy * (Ww * 8) + (size_t)(x0 + lane) * 8;
    ((float4*)p0)[0] = make_float4(o0[0], o0[1], o0[2], o0[3]);
    ((float4*)p0)[1] = make_float4(o0[4], o0[5], o0[6], o0[7]);
    float* p1 = p0 + plane;
    ((float4*)p1)[0] = make_float4(o1[0], o1[1], o1[2], o1[3]);
    ((float4*)p1)[1] = make_float4(o1[4], o1[5], o1[6], o1[7]);
}

// ---------------------------------------------------------------------------
extern "C" void kernel_launch(void* const* d_in, const int* in_sizes, int n_in,
                              void* d_out, int out_size) {
    const float* fmap1  = (const float*)d_in[0];
    const float* fmap2  = (const float*)d_in[1];
    const float* coords = (const float*)d_in[2];
    const float* flow   = (const float*)d_in[3];
    const float* mask   = (const float*)d_in[4];
    float* out = (float*)d_out;

    dim3 tb(32, 8);
    dim3 tg(HWv / 32, Cc / 32, Bb);
    transpose_f_k<<<tg, tb>>>(fmap1);
    transpose_h_k<<<tg, tb>>>(fmap2);
    pool_k<<<dim3(H1 * W1, Bb), 128>>>(1);
    pool_k<<<dim3(H2 * W2, Bb), 128>>>(2);
    pool_k<<<dim3(H3 * W3, Bb), 128>>>(3);
    lookup_k<<<dim3(Ww / 4, Hh / 2, Bb), 256>>>(coords);
    corr_t_k<<<dim3(HWv / 32, 11, Bb), tb>>>(out);
    upsample_k<<<Nn / 32, 256>>>(flow, mask, out);
}

// round 13
// speedup vs baseline: 1.2747x; 1.0450x over previous
#include <cuda_runtime.h>
#include <cuda_fp16.h>
#include <cstdint>

// Problem constants
constexpr int Bb  = 2;
constexpr int Cc  = 256;
constexpr int Hh  = 56;
constexpr int Ww  = 96;
constexpr int HWv = Hh * Ww;          // 5376
constexpr int Nn  = Bb * HWv;         // 10752

// Pyramid dims
constexpr int H1 = 28, W1 = 48;
constexpr int H2 = 14, W2 = 24;
constexpr int H3 = 7,  W3 = 12;

// fp16 channels-last maps: query map + fmap2 pyramid; compact corr scratch
__device__ __half g_f1h[(size_t)Bb * HWv * Cc];
__device__ __half g_f20[(size_t)Bb * HWv * Cc];
__device__ __half g_f21[(size_t)Bb * H1 * W1 * Cc];
__device__ __half g_f22[(size_t)Bb * H2 * W2 * Cc];
__device__ __half g_f23[(size_t)Bb * H3 * W3 * Cc];
__device__ float  g_corr[(size_t)Nn * 324];

// ---------------------------------------------------------------------------
// Transpose [B, C, HW] -> [B, HW, C] with fp32 -> fp16 convert
// which == 0 -> g_f1h (query map), which == 1 -> g_f20 (fmap2 level 0)
// ---------------------------------------------------------------------------
__global__ void transpose_h_k(const float* __restrict__ in, int which) {
    __shared__ float tile[32][33];
    __half* out = which ? g_f20 : g_f1h;
    int b   = blockIdx.z;
    int hw0 = blockIdx.x * 32;
    int c0  = blockIdx.y * 32;
    const float* ib = in  + (size_t)b * Cc * HWv;
    __half*      ob = out + (size_t)b * HWv * Cc;
    int tx = threadIdx.x, ty = threadIdx.y;   // 32 x 8
#pragma unroll
    for (int r = 0; r < 32; r += 8)
        tile[ty + r][tx] = ib[(size_t)(c0 + ty + r) * HWv + hw0 + tx];
    __syncthreads();
#pragma unroll
    for (int r = 0; r < 32; r += 8)
        ob[(size_t)(hw0 + ty + r) * Cc + c0 + tx] = __float2half_rn(tile[tx][ty + r]);
}

// ---------------------------------------------------------------------------
// 2x2 avg pool on channels-last fp16 layout. 128 threads = 128 half2 lanes.
// ---------------------------------------------------------------------------
__global__ void pool_k(int level) {
    const __half* in; __half* out; int Wi, Wo, Ho;
    if (level == 1)      { in = g_f20; out = g_f21; Wi = 96; Wo = 48; Ho = 28; }
    else if (level == 2) { in = g_f21; out = g_f22; Wi = 48; Wo = 24; Ho = 14; }
    else                 { in = g_f22; out = g_f23; Wi = 24; Wo = 12; Ho = 7;  }
    int HiWi = (2 * Ho) * Wi;
    int HoWo = Ho * Wo;
    int b = blockIdx.y, p = blockIdx.x, c = threadIdx.x;   // c in [0,128) half2 units
    int y = p / Wo, x = p - y * Wo;
    const __half2* ib = (const __half2*)(in + (size_t)b * HiWi * Cc);
    size_t i00 = ((size_t)(2 * y) * Wi + 2 * x) * (Cc / 2) + c;
    size_t rs  = (size_t)Wi * (Cc / 2);
    float2 v0 = __half22float2(ib[i00]);
    float2 v1 = __half22float2(ib[i00 + Cc / 2]);
    float2 v2 = __half22float2(ib[i00 + rs]);
    float2 v3 = __half22float2(ib[i00 + rs + Cc / 2]);
    float2 s;
    s.x = 0.25f * (v0.x + v1.x + v2.x + v3.x);
    s.y = 0.25f * (v0.y + v1.y + v2.y + v3.y);
    ((__half2*)(out + ((size_t)b * HoWo + p) * Cc))[c] = __floats2half2_rn(s.x, s.y);
}

// ---------------------------------------------------------------------------
// Correlation lookup — warp-autonomous tensor-core version.
// One block = 4x2 tile of 8 pixels, 8 warps; warp w owns pixel w entirely.
// Per level: 100-position window = 7 mma tiles of 16 positions (112 padded).
// Channels k-chunked at 64: per chunk the warp cp.asyncs 16 pos x 128B into
// its own double-buffered SMEM slice (per-thread cp.async groups -> fully
// warp-scoped pipeline), then 4x (ldmatrix.x4 + mma.m16n8k16), query
// replicated across n, col 0 extracted. NO __syncthreads anywhere.
// Tensor core does the f16->f32 conversion for free (the scalar version was
// conversion-pipe bound at ~0.5 F2F/cyc/SM).
// ---------------------------------------------------------------------------
constexpr int RSTR = 72;             // halves per staged row (144B: 16B pad)
constexpr int WBUF = 16 * RSTR;      // halves per buffer (one 16-pos chunk)

__global__ __launch_bounds__(256) void lookup_k(const float* __restrict__ coords) {
    __shared__ __half   sA[8][2][WBUF];   // 36864 B per-warp double buffers
    __shared__ __half   sQ[8][256];       // 4096 B queries
    __shared__ float    sD[8][112];       // 3584 B window dots
    __shared__ unsigned sOff[8][112];     // 3584 B clamped column offsets
    // total 48128 B static

    int b    = blockIdx.z;
    int t    = threadIdx.x;
    int w    = t >> 5;            // warp = pixel within 4x2 tile
    int lane = t & 31;

    int pxx = blockIdx.x * 4 + (w & 3);
    int pyy = blockIdx.y * 2 + (w >> 2);
    int rem = pyy * Ww + pxx;
    int n   = b * HWv + rem;

    // query (512B) into per-warp SMEM, coalesced
    {
        const unsigned* src = (const unsigned*)(g_f1h + (size_t)n * Cc);
        ((unsigned*)sQ[w])[lane]      = src[lane];
        ((unsigned*)sQ[w])[lane + 32] = src[lane + 32];
        ((unsigned*)sQ[w])[lane + 64] = src[lane + 64];
        ((unsigned*)sQ[w])[lane + 96] = src[lane + 96];
    }

    float cx = coords[(size_t)b * 2 * HWv + rem];
    float cy = coords[(size_t)b * 2 * HWv + HWv + rem];

    const __half* lp[4] = { g_f20, g_f21, g_f22, g_f23 };
    const int Hs[4] = { Hh, H1, H2, H3 };
    const int Ws[4] = { Ww, W1, W2, W3 };

    unsigned bufb = (unsigned)__cvta_generic_to_shared(&sA[w][0][0]);
    unsigned arow_off = (unsigned)(((lane & 15) * RSTR + ((lane >> 4) << 3)) * 2);

#pragma unroll 1
    for (int l = 0; l < 4; l++) {
        float inv = 1.0f / (float)(1 << l);
        float px = cx * inv, py = cy * inv;
        float fx = floorf(px), fy = floorf(py);
        int x0 = (int)fx, y0 = (int)fy;
        float wx = px - fx, wy = py - fy;
        int Hl = Hs[l], Wl = Ws[l];
        const __half* base = lp[l] + (size_t)b * Hl * Wl * Cc;

        // clamped offsets for 112 (padded) positions
#pragma unroll
        for (int i = 0; i < 4; i++) {
            int p = lane + 32 * i;
            if (p < 112) {
                int pc = min(p, 99);
                int xi = pc / 10, yj = pc - xi * 10;
                int cgx = min(max(x0 - 4 + xi, 0), Wl - 1);
                int cgy = min(max(y0 - 4 + yj, 0), Hl - 1);
                sOff[w][p] = (unsigned)((cgy * Wl + cgx) * Cc);
            }
        }
        __syncwarp();

        // stage chunk 0 (tile 0, kc 0)
        {
            unsigned dst = bufb;
            const __half* bsrc = base;
#pragma unroll
            for (int i = 0; i < 4; i++) {
                int unit = i * 32 + lane;
                int pos  = unit >> 3;
                int o16  = unit & 7;
                const __half* src = bsrc + sOff[w][pos] + o16 * 8;
                unsigned da = dst + (unsigned)((pos * RSTR + o16 * 8) * 2);
                asm volatile("cp.async.ca.shared.global [%0], [%1], 16;"
                             :: "r"(da), "l"(src));
            }
            asm volatile("cp.async.commit_group;");
        }

        float acc0 = 0.f, acc1 = 0.f, acc2 = 0.f, acc3 = 0.f;

#pragma unroll 1
        for (int c = 0; c < 28; c++) {          // chunk = tile*4 + kc
            if (c < 27) {
                int cn = c + 1;
                int tilen = cn >> 2, kcn = cn & 3;
                unsigned dst = bufb + (unsigned)((cn & 1) * WBUF * 2);
                const __half* bsrc = base + kcn * 64;
                const unsigned* offs = &sOff[w][tilen * 16];
#pragma unroll
                for (int i = 0; i < 4; i++) {
                    int unit = i * 32 + lane;
                    int pos  = unit >> 3;
                    int o16  = unit & 7;
                    const __half* src = bsrc + offs[pos] + o16 * 8;
                    unsigned da = dst + (unsigned)((pos * RSTR + o16 * 8) * 2);
                    asm volatile("cp.async.ca.shared.global [%0], [%1], 16;"
                                 :: "r"(da), "l"(src));
                }
                asm volatile("cp.async.commit_group;");
                asm volatile("cp.async.wait_group 1;");
            } else {
                asm volatile("cp.async.wait_group 0;");
            }
            __syncwarp();   // publish staged data across lanes

            int kc = c & 3;
            unsigned arow = bufb + (unsigned)((c & 1) * WBUF * 2) + arow_off;
#pragma unroll
            for (int ks = 0; ks < 4; ks++) {
                unsigned a0, a1, a2, a3;
                asm volatile(
                    "ldmatrix.sync.aligned.m8n8.x4.shared.b16 {%0,%1,%2,%3}, [%4];"
                    : "=r"(a0), "=r"(a1), "=r"(a2), "=r"(a3)
                    : "r"(arow + (unsigned)(ks * 32)));
                int kg = kc * 4 + ks;
                unsigned bq0 = *(const unsigned*)&sQ[w][kg * 16 + 2 * (lane & 3)];
                unsigned bq1 = *(const unsigned*)&sQ[w][kg * 16 + 2 * (lane & 3) + 8];
                asm volatile(
                    "mma.sync.aligned.m16n8k16.row.col.f32.f16.f16.f32 "
                    "{%0,%1,%2,%3}, {%4,%5,%6,%7}, {%8,%9}, {%0,%1,%2,%3};"
                    : "+f"(acc0), "+f"(acc1), "+f"(acc2), "+f"(acc3)
                    : "r"(a0), "r"(a1), "r"(a2), "r"(a3), "r"(bq0), "r"(bq1));
            }

            if (kc == 3) {
                // tile done: extract col 0 (lanes lane%4==0: acc0 row r, acc2 row r+8)
                int tile = c >> 2;
                if ((lane & 3) == 0) {
                    int r0 = tile * 16 + (lane >> 2);
                    int r1 = r0 + 8;
                    // recompute validity (warp-uniform x0,y0 in regs)
                    int xi0 = r0 / 10, yj0 = r0 - xi0 * 10;
                    int gx0 = x0 - 4 + xi0, gy0 = y0 - 4 + yj0;
                    float v0 = ((gx0 >= 0) & (gx0 < Wl) & (gy0 >= 0) & (gy0 < Hl)
                                & (r0 < 100)) ? 0.0625f : 0.f;
                    int xi1 = r1 / 10, yj1 = r1 - xi1 * 10;
                    int gx1 = x0 - 4 + xi1, gy1 = y0 - 4 + yj1;
                    float v1 = ((gx1 >= 0) & (gx1 < Wl) & (gy1 >= 0) & (gy1 < Hl)
                                & (r1 < 100)) ? 0.0625f : 0.f;
                    sD[w][r0] = acc0 * v0;
                    sD[w][r1] = acc2 * v1;
                }
                acc0 = acc1 = acc2 = acc3 = 0.f;
            }
        }
        __syncwarp();

        // bilinear combine: owning warp emits its 81 outputs
        for (int u = lane; u < 81; u += 32) {
            int ix = u / 9, iy = u - ix * 9;
            float d00 = sD[w][ix * 10 + iy];
            float d10 = sD[w][ix * 10 + 10 + iy];
            float d01 = sD[w][ix * 10 + iy + 1];
            float d11 = sD[w][ix * 10 + 11 + iy];
            float v = (1.f - wy) * ((1.f - wx) * d00 + wx * d10)
                    +        wy  * ((1.f - wx) * d01 + wx * d11);
            g_corr[(size_t)n * 324 + l * 81 + u] = v;
        }
        __syncwarp();   // sD/sOff reuse in next level
    }
}

// ---------------------------------------------------------------------------
// Transpose compact corr [B*HW][324] -> out [B][324][HW] (coalesced both sides)
// ---------------------------------------------------------------------------
__global__ void corr_t_k(float* __restrict__ out) {
    __shared__ float tile[32][33];
    int b  = blockIdx.z;
    int r0 = blockIdx.x * 32;   // rem tile
    int c0 = blockIdx.y * 32;   // channel tile (0..323)
    int tx = threadIdx.x, ty = threadIdx.y;   // 32 x 8
#pragma unroll
    for (int r = 0; r < 32; r += 8) {
        int c = c0 + tx;
        float v = 0.f;
        if (c < 324)
            v = g_corr[((size_t)b * HWv + r0 + ty + r) * 324 + c];
        tile[ty + r][tx] = v;
    }
    __syncthreads();
#pragma unroll
    for (int r = 0; r < 32; r += 8) {
        int c = c0 + ty + r;
        if (c < 324)
            out[((size_t)b * 324 + c) * HWv + r0 + tx] = tile[tx][ty + r];
    }
}

// ---------------------------------------------------------------------------
// Convex upsample, coalesced. One block = 32 consecutive coarse pixels in a
// row. 256 threads: warp = subpixel row p8, lane = pixel.
// ---------------------------------------------------------------------------
__global__ __launch_bounds__(256) void upsample_k(const float* __restrict__ flow,
                                                  const float* __restrict__ mask,
                                                  float* __restrict__ out) {
    int rem0 = blockIdx.x * 32;
    int b  = rem0 / HWv;
    int r  = rem0 - b * HWv;
    int y  = r / Ww;
    int x0 = r - y * Ww;

    __shared__ float pfc[2][3][34];   // 3x3 neighborhoods of 8*flow for 32 pixels
    int t = threadIdx.x;
    if (t < 204) {
        int ch = t / 102, q = t - ch * 102;
        int dy = q / 34,  dx = q - dy * 34;
        int gy = y - 1 + dy, gx = x0 - 1 + dx;
        float v = 0.f;
        if (gy >= 0 && gy < Hh && gx >= 0 && gx < Ww)
            v = 8.f * flow[((size_t)b * 2 + ch) * HWv + gy * Ww + gx];
        pfc[ch][dy][dx] = v;
    }
    __syncthreads();

    int w = t >> 5;        // p8 (subpixel row)
    int lane = t & 31;     // pixel within the 32-pixel strip
    int rem = r + lane;
    const float* mb = mask + (size_t)b * 576 * HWv + rem;

    float o0[8], o1[8];
#pragma unroll
    for (int q8 = 0; q8 < 8; q8++) {
        float mv[9];
        float mmax = -1e30f;
#pragma unroll
        for (int k = 0; k < 9; k++) {
            mv[k] = mb[(size_t)(k * 64 + w * 8 + q8) * HWv];
            mmax = fmaxf(mmax, mv[k]);
        }
        float se = 0.f;
#pragma unroll
        for (int k = 0; k < 9; k++) { mv[k] = __expf(mv[k] - mmax); se += mv[k]; }
        float rr = 1.f / se;
        float s0 = 0.f, s1 = 0.f;
#pragma unroll
        for (int k = 0; k < 9; k++) {
            int i = k / 3, j = k - i * 3;
            s0 += mv[k] * pfc[0][i][lane + j];
            s1 += mv[k] * pfc[1][i][lane + j];
        }
        o0[q8] = s0 * rr;
        o1[q8] = s1 * rr;
    }

    size_t OFFU  = (size_t)Bb * 324 * HWv;
    size_t plane = (size_t)(Hh * 8) * (Ww * 8);
    int oy = y * 8 + w;
    float* p0 = out + OFFU + (size_t)b * 2 * plane
              + (size_t)oy * (Ww * 8) + (size_t)(x0 + lane) * 8;
    ((float4*)p0)[0] = make_float4(o0[0], o0[1], o0[2], o0[3]);
    ((float4*)p0)[1] = make_float4(o0[4], o0[5], o0[6], o0[7]);
    float* p1 = p0 + plane;
    ((float4*)p1)[0] = make_float4(o1[0], o1[1], o1[2], o1[3]);
    ((float4*)p1)[1] = make_float4(o1[4], o1[5], o1[6], o1[7]);
}

// ---------------------------------------------------------------------------
extern "C" void kernel_launch(void* const* d_in, const int* in_sizes, int n_in,
                              void* d_out, int out_size) {
    const float* fmap1  = (const float*)d_in[0];
    const float* fmap2  = (const float*)d_in[1];
    const float* coords = (const float*)d_in[2];
    const float* flow   = (const float*)d_in[3];
    const float* mask   = (const float*)d_in[4];
    float* out = (float*)d_out;

    dim3 tb(32, 8);
    dim3 tg(HWv / 32, Cc / 32, Bb);
    transpose_h_k<<<tg, tb>>>(fmap1, 0);
    transpose_h_k<<<tg, tb>>>(fmap2, 1);
    pool_k<<<dim3(H1 * W1, Bb), 128>>>(1);
    pool_k<<<dim3(H2 * W2, Bb), 128>>>(2);
    pool_k<<<dim3(H3 * W3, Bb), 128>>>(3);
    lookup_k<<<dim3(Ww / 4, Hh / 2, Bb), 256>>>(coords);
    corr_t_k<<<dim3(HWv / 32, 11, Bb), tb>>>(out);
    upsample_k<<<Nn / 32, 256>>>(flow, mask, out);
}